// round 16
// baseline (speedup 1.0000x reference)
#include <cuda_runtime.h>
#include <cuda_bf16.h>
#include <cstdint>

// Problem constants
#define L_Q  128
#define N_B  8
#define S_P  16384
#define C_D  256
#define SN_ROWS (S_P * N_B)   // 131072
#define LN_ROWS (L_Q * N_B)   // 1024
#define MARGIN  0.30f
#define CAND_CAP (1u << 20)
#define POOL_CAP (1u << 22)

// ---------------- scratch ----------------
__device__ float          g_qproj[LN_ROWS * C_D];            // exact fp32 q_proj [l*8+n][c]
__device__ __nv_bfloat16  g_qb[LN_ROWS * C_D];               // bf16 q_proj [n][l][c]
__device__ __nv_bfloat16  g_wpb[C_D * C_D];                  // bf16 Wp
__device__ uint2          g_pool[POOL_CAP];                  // {packed, logit_bits}
__device__ unsigned       g_npool;
__device__ unsigned       g_amax[LN_ROWS];                   // mapped-float global approx max
__device__ unsigned       g_cand[CAND_CAP];                  // packed (s<<10)|(l<<3)|n
__device__ unsigned       g_ncand;
__device__ unsigned long long g_argmax[LN_ROWS];             // packed (mapped_exact<<32)|~s

// ---------------- helpers ----------------
static __device__ __forceinline__ unsigned fmap(float x) {
    unsigned m = __float_as_uint(x);
    return (m & 0x80000000u) ? ~m : (m | 0x80000000u);
}
static __device__ __forceinline__ float funmap(unsigned u) {
    return __uint_as_float((u & 0x80000000u) ? (u ^ 0x80000000u) : ~u);
}
static __device__ __forceinline__ void mma_bf16(float c[4], const unsigned a[4],
                                                unsigned b0, unsigned b1) {
    asm volatile("mma.sync.aligned.m16n8k16.row.col.f32.bf16.bf16.f32 "
                 "{%0,%1,%2,%3}, {%4,%5,%6,%7}, {%8,%9}, {%0,%1,%2,%3};"
                 : "+f"(c[0]), "+f"(c[1]), "+f"(c[2]), "+f"(c[3])
                 : "r"(a[0]), "r"(a[1]), "r"(a[2]), "r"(a[3]), "r"(b0), "r"(b1));
}
static __device__ __forceinline__ void ldsm4(unsigned* r, uint32_t addr) {
    asm volatile("ldmatrix.sync.aligned.m8n8.x4.shared.b16 {%0,%1,%2,%3}, [%4];"
                 : "=r"(r[0]), "=r"(r[1]), "=r"(r[2]), "=r"(r[3]) : "r"(addr));
}
static __device__ __forceinline__ void cp16(void* smem_dst, const void* gsrc) {
    unsigned d = (unsigned)__cvta_generic_to_shared(smem_dst);
    asm volatile("cp.async.cg.shared.global [%0], [%1], 16;\n" :: "r"(d), "l"(gsrc));
}
static __device__ __forceinline__ void cp_commit() {
    asm volatile("cp.async.commit_group;\n" ::: "memory");
}
static __device__ __forceinline__ void cp_wait0() {
    asm volatile("cp.async.wait_group 0;\n" ::: "memory");
}
static __device__ __forceinline__ unsigned pkbf(float x, float y) {
    __nv_bfloat162 h = __floats2bfloat162_rn(x, y);
    return *(unsigned*)&h;
}

// Swizzled byte offset inside a [rows][256 bf16] tile (512B per row):
#define SWZB(row, unit) (((row) << 9) + ((((unit) ^ ((row) & 7))) << 4))
// 4B-pair store offset for (row m, even col jc):
#define KPB(m, jc) (((m) << 9) + (((((jc) >> 3) ^ ((m) & 7))) << 4) + (((jc) & 7) << 1))

// ---------------- K0: init + Wp->bf16 ----------------
__global__ void init_kernel(const float* __restrict__ Wp) {
    int i = blockIdx.x * blockDim.x + threadIdx.x;   // 65536
    g_wpb[i] = __float2bfloat16(Wp[i]);
    if (i < LN_ROWS) { g_amax[i] = 0u; g_argmax[i] = 0ull; }
    if (i == 0) { g_ncand = 0u; g_npool = 0u; }
}

// ---------------- K1: exact fp32 q_proj (+ bf16 copy, [n][l][c]) ----------------
__global__ __launch_bounds__(256) void qproj_kernel(
    const float* __restrict__ tgt, const float* __restrict__ qpos,
    const float* __restrict__ Wq,  const float* __restrict__ bq)
{
    __shared__ float a_s[8][256];
    const int t  = threadIdx.x;
    const int r0 = blockIdx.x * 8;
#pragma unroll
    for (int r = 0; r < 8; ++r)
        a_s[r][t] = tgt[(size_t)(r0 + r) * 256 + t] + qpos[(size_t)(r0 + r) * 256 + t];
    __syncthreads();
    float acc[8];
#pragma unroll
    for (int r = 0; r < 8; ++r) acc[r] = bq[t];
    const float4* w4 = (const float4*)&Wq[(size_t)t * 256];
#pragma unroll 4
    for (int k4 = 0; k4 < 64; ++k4) {
        const float4 w = w4[k4];
#pragma unroll
        for (int r = 0; r < 8; ++r) {
            const float4 a = *(const float4*)&a_s[r][k4 * 4];
            acc[r] += a.x * w.x + a.y * w.y + a.z * w.z + a.w * w.w;
        }
    }
#pragma unroll
    for (int r = 0; r < 8; ++r) {
        const int row = r0 + r;            // = l*8 + n
        const int l = row >> 3, n = row & 7;
        g_qproj[(size_t)row * 256 + t] = acc[r];
        g_qb[((size_t)n * L_Q + l) * 256 + t] = __float2bfloat16(acc[r]);
    }
}

// ---------------- K2: FUSED k_proj + normalize + logits + candidates ----------
// 64 s-rows per CTA, 256 threads (8 warps: 2 m-groups x 4 n-groups), 2 CTAs/SM.
//   AS [0,     32768): A = bf16(mem+pos) 64x256, SWZB
//   WQ [32768, 65536): Wp j-chunk (64x256) / q l-chunk (64x256), SWZB
//   KP [65536, 98304): kp tile 64x256 bf16 (bias added, unnormalized), SWZB
#define OF_ROW  98304
#define OF_BSM  98560
#define OF_AMX  99584
#define OF_THR  99840
#define OF_WT   100096
#define OF_WO   100128
#define OF_BASE 100160
#define FU_SMEM 100352
__global__ __launch_bounds__(256, 2) void fused_kernel(
    const float* __restrict__ mem, const float* __restrict__ pos,
    const float* __restrict__ bp)
{
    extern __shared__ char sm[];
    const uint32_t smu = (uint32_t)__cvta_generic_to_shared(sm);
    char* AS = sm;
    char* WQ = sm + 32768;
    char* KP = sm + 65536;
    float*    rowss  = (float*)(sm + OF_ROW);      // [64] sumsq -> invnorm
    float*    bsm    = (float*)(sm + OF_BSM);      // [256]
    unsigned* amax_s = (unsigned*)(sm + OF_AMX);   // [64]
    float*    thr_s  = (float*)(sm + OF_THR);      // [64]
    unsigned* wtot   = (unsigned*)(sm + OF_WT);    // [8]
    unsigned* woff   = (unsigned*)(sm + OF_WO);    // [8]
    unsigned* base_s = (unsigned*)(sm + OF_BASE);

    const uint32_t AS_u = smu, WQ_u = smu + 32768, KP_u = smu + 65536;
    const int t = threadIdx.x, lane = t & 31, wid = t >> 5;
    const int g = lane >> 2, tid4 = lane & 3;
    const int wm = wid >> 2;          // 0..1  (m rows, 32 each)
    const int wn = wid & 3;           // 0..3  (j/l cols, 16 each)
    const int s0 = blockIdx.x * 64;
    const int n  = blockIdx.y;

    // ldmatrix per-lane address constants
    const int xL    = lane & 7;
    const int aLrow = (lane & 7) + ((lane >> 3) & 1) * 8;
    const int aDu   = lane >> 4;
    const int bLrow = (lane & 7) + (lane >> 4) * 8;
    const int bDu   = (lane >> 3) & 1;

    if (t < 64) { rowss[t] = 0.f; }
    bsm[t] = bp[t];

    // ---- stage Wp j-chunk 0 (async) ----
#pragma unroll
    for (int i = 0; i < 8; ++i) {
        const int id = t + i * 256, r = id >> 5, u = id & 31;
        cp16(WQ + SWZB(r, u), &g_wpb[(size_t)r * 256 + u * 8]);
    }
    cp_commit();

    // ---- stage A = bf16(mem+pos), SWZB (LDG overlaps cp.async) ----
#pragma unroll
    for (int i = 0; i < 8; ++i) {
        const int id = t + i * 256, r = id >> 5, u = id & 31;
        const size_t base = ((size_t)(s0 + r) * 8 + n) * 256 + u * 8;
        const float4 m0 = *(const float4*)&mem[base];
        const float4 m1 = *(const float4*)&mem[base + 4];
        const float4 p0 = *(const float4*)&pos[base];
        const float4 p1 = *(const float4*)&pos[base + 4];
        uint4 v;
        v.x = pkbf(m0.x + p0.x, m0.y + p0.y);
        v.y = pkbf(m0.z + p0.z, m0.w + p0.w);
        v.z = pkbf(m1.x + p1.x, m1.y + p1.y);
        v.w = pkbf(m1.z + p1.z, m1.w + p1.w);
        *(uint4*)(AS + SWZB(r, u)) = v;
    }

    // fragment smem base addresses
    uint32_t aBase[2], kpBase[2];
#pragma unroll
    for (int mf = 0; mf < 2; ++mf) {
        const int row = wm * 32 + mf * 16 + aLrow;
        aBase[mf]  = AS_u + (row << 9);
        kpBase[mf] = KP_u + (row << 9);
    }
    const uint32_t bBase = WQ_u + ((wn * 16 + bLrow) << 9);

    // ================= Phase 1: kp = A @ Wp^T (+bias), 4 j-chunks of 64 ==========
#pragma unroll 1
    for (int jblk = 0; jblk < 4; ++jblk) {
        if (jblk > 0) {
            __syncthreads();   // prior WQ reads done
#pragma unroll
            for (int i = 0; i < 8; ++i) {
                const int id = t + i * 256, r = id >> 5, u = id & 31;
                cp16(WQ + SWZB(r, u), &g_wpb[(size_t)(jblk * 64 + r) * 256 + u * 8]);
            }
            cp_commit();
        }
        cp_wait0();
        __syncthreads();

        float acc[2][2][4];
#pragma unroll
        for (int mf = 0; mf < 2; ++mf)
#pragma unroll
            for (int nf = 0; nf < 2; ++nf)
#pragma unroll
                for (int c = 0; c < 4; ++c) acc[mf][nf][c] = 0.f;

#pragma unroll
        for (int kk = 0; kk < 16; ++kk) {
            const uint32_t offA = (uint32_t)(((2 * kk + aDu) ^ xL) << 4);
            const uint32_t offB = (uint32_t)(((2 * kk + bDu) ^ xL) << 4);
            unsigned b[4];
            ldsm4(b, bBase + offB);
#pragma unroll
            for (int mf = 0; mf < 2; ++mf) {
                unsigned a[4];
                ldsm4(a, aBase[mf] + offA);
                mma_bf16(acc[mf][0], a, b[0], b[1]);
                mma_bf16(acc[mf][1], a, b[2], b[3]);
            }
        }

        // epilogue: +bias, sum-sq, store bf16 kp tile
#pragma unroll
        for (int mf = 0; mf < 2; ++mf) {
            const int m0 = wm * 32 + mf * 16 + g, m1 = m0 + 8;
            float ss0 = 0.f, ss1 = 0.f;
#pragma unroll
            for (int nf = 0; nf < 2; ++nf) {
                const int jc = jblk * 64 + wn * 16 + nf * 8 + 2 * tid4;
                const float b0v = bsm[jc], b1v = bsm[jc + 1];
                const float v00 = acc[mf][nf][0] + b0v, v01 = acc[mf][nf][1] + b1v;
                const float v10 = acc[mf][nf][2] + b0v, v11 = acc[mf][nf][3] + b1v;
                ss0 += v00 * v00 + v01 * v01;
                ss1 += v10 * v10 + v11 * v11;
                *(unsigned*)(KP + KPB(m0, jc)) = pkbf(v00, v01);
                *(unsigned*)(KP + KPB(m1, jc)) = pkbf(v10, v11);
            }
            ss0 += __shfl_xor_sync(0xffffffffu, ss0, 1);
            ss0 += __shfl_xor_sync(0xffffffffu, ss0, 2);
            ss1 += __shfl_xor_sync(0xffffffffu, ss1, 1);
            ss1 += __shfl_xor_sync(0xffffffffu, ss1, 2);
            if (tid4 == 0) {
                atomicAdd(&rowss[m0], ss0);
                atomicAdd(&rowss[m1], ss1);
            }
        }
    }
    __syncthreads();
    if (t < 64) rowss[t] = 1.0f / fmaxf(sqrtf(rowss[t]), 1e-12f);

    // ================= Phase 2: logits, per 64-l chunk ==========================
#pragma unroll 1
    for (int lchunk = 0; lchunk < 2; ++lchunk) {
        __syncthreads();   // WQ free; rowss ready (first iter)
        if (t < 64) amax_s[t] = 0u;
#pragma unroll
        for (int i = 0; i < 8; ++i) {
            const int id = t + i * 256, r = id >> 5, u = id & 31;
            cp16(WQ + SWZB(r, u),
                 &g_qb[((size_t)n * L_Q + lchunk * 64 + r) * 256 + u * 8]);
        }
        cp_commit();
        cp_wait0();
        __syncthreads();

        float acc[2][2][4];
#pragma unroll
        for (int mf = 0; mf < 2; ++mf)
#pragma unroll
            for (int nf = 0; nf < 2; ++nf)
#pragma unroll
                for (int c = 0; c < 4; ++c) acc[mf][nf][c] = 0.f;

#pragma unroll
        for (int kk = 0; kk < 16; ++kk) {
            const uint32_t offA = (uint32_t)(((2 * kk + aDu) ^ xL) << 4);
            const uint32_t offB = (uint32_t)(((2 * kk + bDu) ^ xL) << 4);
            unsigned b[4];
            ldsm4(b, bBase + offB);
#pragma unroll
            for (int mf = 0; mf < 2; ++mf) {
                unsigned a[4];
                ldsm4(a, kpBase[mf] + offA);
                mma_bf16(acc[mf][0], a, b[0], b[1]);
                mma_bf16(acc[mf][1], a, b[2], b[3]);
            }
        }

        // scale by 1/norm (rows = s)
#pragma unroll
        for (int mf = 0; mf < 2; ++mf) {
            const int r0 = wm * 32 + mf * 16 + g;
            const float inv0 = rowss[r0], inv1 = rowss[r0 + 8];
#pragma unroll
            for (int nf = 0; nf < 2; ++nf) {
                acc[mf][nf][0] *= inv0; acc[mf][nf][1] *= inv0;
                acc[mf][nf][2] *= inv1; acc[mf][nf][3] *= inv1;
            }
        }

        // CTA-local per-l max (reduce over m: lanes g and both mf/halves)
#pragma unroll
        for (int nf = 0; nf < 2; ++nf) {
            float me = acc[0][nf][0], mo = acc[0][nf][1];
#pragma unroll
            for (int mf = 0; mf < 2; ++mf) {
                me = fmaxf(me, fmaxf(acc[mf][nf][0], acc[mf][nf][2]));
                mo = fmaxf(mo, fmaxf(acc[mf][nf][1], acc[mf][nf][3]));
            }
#pragma unroll
            for (int off = 4; off < 32; off <<= 1) {
                me = fmaxf(me, __shfl_xor_sync(0xffffffffu, me, off));
                mo = fmaxf(mo, __shfl_xor_sync(0xffffffffu, mo, off));
            }
            if (lane < 4) {
                const int lc = wn * 16 + nf * 8 + 2 * lane;
                atomicMax(&amax_s[lc],     fmap(me));
                atomicMax(&amax_s[lc + 1], fmap(mo));
            }
        }
        __syncthreads();
        if (t < 64) {
            atomicMax(&g_amax[(lchunk * 64 + t) * 8 + n], amax_s[t]);
            thr_s[t] = funmap(amax_s[t]) - MARGIN;
        }
        __syncthreads();

        // candidate count + scan + pool write (chunk-local l's)
        int cnt = 0;
#pragma unroll
        for (int mf = 0; mf < 2; ++mf)
#pragma unroll
            for (int nf = 0; nf < 2; ++nf)
#pragma unroll
                for (int c = 0; c < 4; ++c) {
                    const int lc = wn * 16 + nf * 8 + 2 * tid4 + (c & 1);
                    if (acc[mf][nf][c] >= thr_s[lc]) ++cnt;
                }
        int incl = cnt;
#pragma unroll
        for (int off = 1; off < 32; off <<= 1) {
            const int x = __shfl_up_sync(0xffffffffu, incl, off);
            if (lane >= off) incl += x;
        }
        if (lane == 31) wtot[wid] = (unsigned)incl;
        __syncthreads();
        if (t == 0) {
            unsigned tot = 0;
#pragma unroll
            for (int w = 0; w < 8; ++w) { woff[w] = tot; tot += wtot[w]; }
            *base_s = atomicAdd(&g_npool, tot);
        }
        __syncthreads();
        unsigned p = *base_s + woff[wid] + (unsigned)(incl - cnt);
#pragma unroll
        for (int mf = 0; mf < 2; ++mf)
#pragma unroll
            for (int nf = 0; nf < 2; ++nf)
#pragma unroll
                for (int c = 0; c < 4; ++c) {
                    const int lc = wn * 16 + nf * 8 + 2 * tid4 + (c & 1);
                    const float v = acc[mf][nf][c];
                    if (v >= thr_s[lc]) {
                        const int sr = s0 + wm * 32 + mf * 16 + g + ((c >= 2) ? 8 : 0);
                        const unsigned lg = (unsigned)(lchunk * 64 + lc);
                        if (p < POOL_CAP)
                            g_pool[p] = make_uint2(((unsigned)sr << 10) |
                                                   (lg << 3) | (unsigned)n,
                                                   __float_as_uint(v));
                        ++p;
                    }
                }
    }
}

// ---------------- K4: filter pool against global approx max ----------------
__global__ __launch_bounds__(256) void filter_kernel()
{
    __shared__ float thr_s[LN_ROWS];
    const int t = threadIdx.x;
    for (int i = t; i < LN_ROWS; i += 256) thr_s[i] = funmap(g_amax[i]) - MARGIN;
    __syncthreads();
    const unsigned np = min(g_npool, (unsigned)POOL_CAP);
    for (unsigned idx = blockIdx.x * 256 + t; idx < np; idx += gridDim.x * 256) {
        const uint2 e = g_pool[idx];
        const unsigned l = (e.x >> 3) & 127u, n = e.x & 7u;
        if (__uint_as_float(e.y) >= thr_s[l * 8 + n]) {
            const unsigned pp = atomicAdd(&g_ncand, 1u);
            if (pp < CAND_CAP) g_cand[pp] = e.x;
        }
    }
}

// ---------------- K5: exact fp32 rescore, batched 32 candidates/CTA ----------------
#define RS_SMEM (32768 + 32896 + 32896)
__global__ __launch_bounds__(256, 1) void rescore_kernel(
    const float* __restrict__ mem, const float* __restrict__ pos,
    const float* __restrict__ Wp,  const float* __restrict__ bp)
{
    extern __shared__ char rsm[];
    float* A   = (float*)rsm;                    // [32][256]
    float* WT  = (float*)(rsm + 32768);          // [kk][o], stride 257
    float* KPS = (float*)(rsm + 65664);          // [ci][t], stride 257
    __shared__ unsigned meta[32];
    __shared__ unsigned count_s;

    const int t = threadIdx.x, lane = t & 31, wid = t >> 5;
    if (t == 0) count_s = min(g_ncand, (unsigned)CAND_CAP);
    __syncthreads();
    const unsigned count = count_s;
    const unsigned nchunks = (count + 31u) >> 5;

    for (unsigned chunk = blockIdx.x; chunk < nchunks; chunk += gridDim.x) {
        __syncthreads();
        if (t < 32)
            meta[t] = (chunk * 32u + t < count) ? g_cand[chunk * 32u + t] : 0xFFFFFFFFu;
        __syncthreads();
#pragma unroll 4
        for (int ci = 0; ci < 32; ++ci) {
            const unsigned pk = meta[ci];
            if (pk != 0xFFFFFFFFu) {
                const size_t rowk = ((size_t)(pk >> 10) * 8 + (pk & 7u)) * 256;
                A[ci * 256 + t] = mem[rowk + t] + pos[rowk + t];
            }
        }
        float acc[32];
        const float bias = bp[t];
#pragma unroll
        for (int ci = 0; ci < 32; ++ci) acc[ci] = bias;

        for (int kt = 0; kt < 8; ++kt) {
            __syncthreads();
#pragma unroll
            for (int i = 0; i < 8; ++i) {
                const int id = t + i * 256, o = id >> 3, k4 = id & 7;
                const float4 w = *(const float4*)&Wp[(size_t)o * 256 + kt * 32 + k4 * 4];
                WT[(k4 * 4 + 0) * 257 + o] = w.x;
                WT[(k4 * 4 + 1) * 257 + o] = w.y;
                WT[(k4 * 4 + 2) * 257 + o] = w.z;
                WT[(k4 * 4 + 3) * 257 + o] = w.w;
            }
            __syncthreads();
            float wt[32];
#pragma unroll
            for (int kk = 0; kk < 32; ++kk) wt[kk] = WT[kk * 257 + t];
#pragma unroll 4
            for (int ci = 0; ci < 32; ++ci) {
                const float4* a4 = (const float4*)&A[ci * 256 + kt * 32];
#pragma unroll
                for (int q = 0; q < 8; ++q) {
                    const float4 av = a4[q];
                    acc[ci] += av.x * wt[q * 4 + 0] + av.y * wt[q * 4 + 1]
                             + av.z * wt[q * 4 + 2] + av.w * wt[q * 4 + 3];
                }
            }
        }
        __syncthreads();
#pragma unroll
        for (int ci = 0; ci < 32; ++ci) KPS[ci * 257 + t] = acc[ci];
        __syncthreads();
#pragma unroll
        for (int cc = 0; cc < 4; ++cc) {
            const int ci = wid * 4 + cc;
            const unsigned pk = meta[ci];
            if (pk == 0xFFFFFFFFu) continue;
            const unsigned s = pk >> 10, l = (pk >> 3) & 127u, n = pk & 7u;
            const float* qrow = &g_qproj[((size_t)l * 8 + n) * 256];
            float ss = 0.f, qd = 0.f;
#pragma unroll
            for (int j = 0; j < 8; ++j) {
                const float kv = KPS[ci * 257 + lane + 32 * j];
                ss += kv * kv;
                qd += qrow[lane + 32 * j] * kv;
            }
#pragma unroll
            for (int off = 16; off > 0; off >>= 1) {
                ss += __shfl_xor_sync(0xffffffffu, ss, off);
                qd += __shfl_xor_sync(0xffffffffu, qd, off);
            }
            if (lane == 0) {
                const float logit = qd / fmaxf(sqrtf(ss), 1e-12f);
                const unsigned long long key =
                    ((unsigned long long)fmap(logit) << 32) |
                    (unsigned long long)(0xFFFFFFFFu - s);
                atomicMax(&g_argmax[l * 8 + n], key);
            }
        }
    }
}

// ---------------- K6: batched finalize — 64 CTAs x 16 rows ----------------
#define FIN_SMEM (16384 + 16384 + 32896)
__global__ __launch_bounds__(256, 1) void finalize_kernel(
    const float* __restrict__ tgt,   const float* __restrict__ memory,
    const float* __restrict__ pos,
    const float* __restrict__ Wp,    const float* __restrict__ bp,
    const float* __restrict__ Wv,    const float* __restrict__ bv,
    const float* __restrict__ Wo,    const float* __restrict__ bo,
    const float* __restrict__ gamma, const float* __restrict__ beta,
    float* __restrict__ out)
{
    extern __shared__ char fsm[];
    float* BUF0 = (float*)fsm;                    // [16][256]
    float* BUF1 = (float*)(fsm + 16384);          // [16][256]
    float* WT   = (float*)(fsm + 32768);          // [32][257]
    __shared__ int sel_s[16];

    const int t = threadIdx.x, lane = t & 31, wid = t >> 5;
    const int base = blockIdx.x * 16;

    if (t < 16) {
        const unsigned long long key = g_argmax[base + t];
        sel_s[t] = (int)(0xFFFFFFFFu - (unsigned)(key & 0xFFFFFFFFull));
    }
    __syncthreads();
#pragma unroll
    for (int r = 0; r < 16; ++r) {
        const size_t rowk = ((size_t)sel_s[r] * 8 + ((base + r) & 7)) * 256;
        BUF0[r * 256 + t] = memory[rowk + t] + pos[rowk + t];
    }
    const float* Ws[3] = {Wp, Wv, Wo};
    const float* bs[3] = {bp, bv, bo};
#pragma unroll
    for (int layer = 0; layer < 3; ++layer) {
        const float* W   = Ws[layer];
        float* INB  = (layer & 1) ? BUF1 : BUF0;
        float* OUTB = (layer & 1) ? BUF0 : BUF1;
        float acc[16];
#pragma unroll
        for (int r = 0; r < 16; ++r) acc[r] = 0.f;
        for (int kt = 0; kt < 8; ++kt) {
            __syncthreads();
#pragma unroll
            for (int i = 0; i < 8; ++i) {
                const int id = t + i * 256, o = id >> 3, k4 = id & 7;
                const float4 w = *(const float4*)&W[(size_t)o * 256 + kt * 32 + k4 * 4];
                WT[(k4 * 4 + 0) * 257 + o] = w.x;
                WT[(k4 * 4 + 1) * 257 + o] = w.y;
                WT[(k4 * 4 + 2) * 257 + o] = w.z;
                WT[(k4 * 4 + 3) * 257 + o] = w.w;
            }
            __syncthreads();
            float wt[32];
#pragma unroll
            for (int kk = 0; kk < 32; ++kk) wt[kk] = WT[kk * 257 + t];
#pragma unroll
            for (int r = 0; r < 16; ++r) {
                const float4* a4 = (const float4*)&INB[r * 256 + kt * 32];
#pragma unroll
                for (int q = 0; q < 8; ++q) {
                    const float4 av = a4[q];
                    acc[r] += av.x * wt[q * 4 + 0] + av.y * wt[q * 4 + 1]
                            + av.z * wt[q * 4 + 2] + av.w * wt[q * 4 + 3];
                }
            }
        }
        __syncthreads();
        const float bias = bs[layer][t];
#pragma unroll
        for (int r = 0; r < 16; ++r)
            OUTB[r * 256 + t] = acc[r] + bias;
    }
    __syncthreads();
#pragma unroll
    for (int rr = 0; rr < 2; ++rr) {
        const int r = wid * 2 + rr;
        const int pair = base + r;
        float xv[8];
        float s = 0.f, s2 = 0.f;
#pragma unroll
        for (int j = 0; j < 8; ++j) {
            const int c = lane + 32 * j;
            xv[j] = tgt[(size_t)pair * 256 + c] + BUF1[r * 256 + c];
            s  += xv[j];
            s2 += xv[j] * xv[j];
        }
#pragma unroll
        for (int off = 16; off > 0; off >>= 1) {
            s  += __shfl_xor_sync(0xffffffffu, s,  off);
            s2 += __shfl_xor_sync(0xffffffffu, s2, off);
        }
        const float mu   = s * (1.0f / 256.0f);
        const float var  = s2 * (1.0f / 256.0f) - mu * mu;
        const float rstd = rsqrtf(var + 1e-5f);
#pragma unroll
        for (int j = 0; j < 8; ++j) {
            const int c = lane + 32 * j;
            out[(size_t)pair * 256 + c] = (xv[j] - mu) * rstd * gamma[c] + beta[c];
        }
    }
}

// ---------------- launch ----------------
extern "C" void kernel_launch(void* const* d_in, const int* in_sizes, int n_in,
                              void* d_out, int out_size)
{
    const float* tgt       = (const float*)d_in[0];
    const float* memory    = (const float*)d_in[1];
    const float* pos       = (const float*)d_in[2];
    const float* query_pos = (const float*)d_in[3];
    const float* Wq        = (const float*)d_in[4];
    const float* bq        = (const float*)d_in[5];
    const float* Wp        = (const float*)d_in[6];
    const float* bp        = (const float*)d_in[7];
    const float* Wv        = (const float*)d_in[8];
    const float* bv        = (const float*)d_in[9];
    const float* Wo        = (const float*)d_in[10];
    const float* bo        = (const float*)d_in[11];
    const float* gamma     = (const float*)d_in[12];
    const float* beta      = (const float*)d_in[13];
    float* out             = (float*)d_out;

    cudaFuncSetAttribute(fused_kernel,
                         cudaFuncAttributeMaxDynamicSharedMemorySize, FU_SMEM);
    cudaFuncSetAttribute(rescore_kernel,
                         cudaFuncAttributeMaxDynamicSharedMemorySize, RS_SMEM);
    cudaFuncSetAttribute(finalize_kernel,
                         cudaFuncAttributeMaxDynamicSharedMemorySize, FIN_SMEM);

    init_kernel<<<256, 256>>>(Wp);
    qproj_kernel<<<LN_ROWS / 8, 256>>>(tgt, query_pos, Wq, bq);
    fused_kernel<<<dim3(S_P / 64, N_B), 256, FU_SMEM>>>(memory, pos, bp);
    filter_kernel<<<512, 256>>>();
    rescore_kernel<<<148, 256, RS_SMEM>>>(memory, pos, Wp, bp);
    finalize_kernel<<<LN_ROWS / 16, 256, FIN_SMEM>>>(tgt, memory, pos, Wp, bp,
                                                     Wv, bv, Wo, bo,
                                                     gamma, beta, out);
}

// round 17
// speedup vs baseline: 1.1231x; 1.1231x over previous
#include <cuda_runtime.h>
#include <cuda_bf16.h>
#include <cstdint>

// Problem constants
#define L_Q  128
#define N_B  8
#define S_P  16384
#define C_D  256
#define SN_ROWS (S_P * N_B)   // 131072
#define LN_ROWS (L_Q * N_B)   // 1024
#define MARGIN  0.30f
#define CAND_CAP (1u << 20)
#define POOL_CAP (1u << 22)

// ---------------- scratch ----------------
__device__ float          g_qproj[LN_ROWS * C_D];            // exact fp32 q_proj [l*8+n][c]
__device__ __nv_bfloat16  g_qb[LN_ROWS * C_D];               // bf16 q_proj [n][l][c]
__device__ __nv_bfloat16  g_wpb[C_D * C_D];                  // bf16 Wp
__device__ uint2          g_pool[POOL_CAP];                  // {packed, logit_bits}
__device__ unsigned       g_npool;
__device__ unsigned       g_amax[LN_ROWS];                   // mapped-float global approx max
__device__ unsigned       g_cand[CAND_CAP];                  // packed (s<<10)|(l<<3)|n
__device__ unsigned       g_ncand;
__device__ unsigned long long g_argmax[LN_ROWS];             // packed (mapped_exact<<32)|~s

// ---------------- helpers ----------------
static __device__ __forceinline__ unsigned fmap(float x) {
    unsigned m = __float_as_uint(x);
    return (m & 0x80000000u) ? ~m : (m | 0x80000000u);
}
static __device__ __forceinline__ float funmap(unsigned u) {
    return __uint_as_float((u & 0x80000000u) ? (u ^ 0x80000000u) : ~u);
}
static __device__ __forceinline__ void mma_bf16(float c[4], const unsigned a[4],
                                                unsigned b0, unsigned b1) {
    asm volatile("mma.sync.aligned.m16n8k16.row.col.f32.bf16.bf16.f32 "
                 "{%0,%1,%2,%3}, {%4,%5,%6,%7}, {%8,%9}, {%0,%1,%2,%3};"
                 : "+f"(c[0]), "+f"(c[1]), "+f"(c[2]), "+f"(c[3])
                 : "r"(a[0]), "r"(a[1]), "r"(a[2]), "r"(a[3]), "r"(b0), "r"(b1));
}
static __device__ __forceinline__ void ldsm4(unsigned* r, uint32_t addr) {
    asm volatile("ldmatrix.sync.aligned.m8n8.x4.shared.b16 {%0,%1,%2,%3}, [%4];"
                 : "=r"(r[0]), "=r"(r[1]), "=r"(r[2]), "=r"(r[3]) : "r"(addr));
}
static __device__ __forceinline__ void cp16(void* smem_dst, const void* gsrc) {
    unsigned d = (unsigned)__cvta_generic_to_shared(smem_dst);
    asm volatile("cp.async.cg.shared.global [%0], [%1], 16;\n" :: "r"(d), "l"(gsrc));
}
static __device__ __forceinline__ void cp_commit() {
    asm volatile("cp.async.commit_group;\n" ::: "memory");
}
static __device__ __forceinline__ void cp_wait0() {
    asm volatile("cp.async.wait_group 0;\n" ::: "memory");
}
static __device__ __forceinline__ unsigned pkbf(float x, float y) {
    __nv_bfloat162 h = __floats2bfloat162_rn(x, y);
    return *(unsigned*)&h;
}

// Swizzled byte offset inside a [rows][256 bf16] tile (512B per row):
#define SWZB(row, unit) (((row) << 9) + ((((unit) ^ ((row) & 7))) << 4))
// 4B-pair store offset for (row m, even col jc):
#define KPB(m, jc) (((m) << 9) + (((((jc) >> 3) ^ ((m) & 7))) << 4) + (((jc) & 7) << 1))

// ---------------- K0: init + Wp->bf16 ----------------
__global__ void init_kernel(const float* __restrict__ Wp) {
    int i = blockIdx.x * blockDim.x + threadIdx.x;   // 65536
    g_wpb[i] = __float2bfloat16(Wp[i]);
    if (i < LN_ROWS) { g_amax[i] = 0u; g_argmax[i] = 0ull; }
    if (i == 0) { g_ncand = 0u; g_npool = 0u; }
}

// ---------------- K1: exact fp32 q_proj (+ bf16 copy, [n][l][c]) ----------------
__global__ __launch_bounds__(256) void qproj_kernel(
    const float* __restrict__ tgt, const float* __restrict__ qpos,
    const float* __restrict__ Wq,  const float* __restrict__ bq)
{
    __shared__ float a_s[8][256];
    const int t  = threadIdx.x;
    const int r0 = blockIdx.x * 8;
#pragma unroll
    for (int r = 0; r < 8; ++r)
        a_s[r][t] = tgt[(size_t)(r0 + r) * 256 + t] + qpos[(size_t)(r0 + r) * 256 + t];
    __syncthreads();
    float acc[8];
#pragma unroll
    for (int r = 0; r < 8; ++r) acc[r] = bq[t];
    const float4* w4 = (const float4*)&Wq[(size_t)t * 256];
#pragma unroll 4
    for (int k4 = 0; k4 < 64; ++k4) {
        const float4 w = w4[k4];
#pragma unroll
        for (int r = 0; r < 8; ++r) {
            const float4 a = *(const float4*)&a_s[r][k4 * 4];
            acc[r] += a.x * w.x + a.y * w.y + a.z * w.z + a.w * w.w;
        }
    }
#pragma unroll
    for (int r = 0; r < 8; ++r) {
        const int row = r0 + r;            // = l*8 + n
        const int l = row >> 3, n = row & 7;
        g_qproj[(size_t)row * 256 + t] = acc[r];
        g_qb[((size_t)n * L_Q + l) * 256 + t] = __float2bfloat16(acc[r]);
    }
}

// ---------------- K2: FUSED k_proj + normalize + logits + candidates ----------
// 256 threads, 8 warps (2 m-groups x 4 n-groups), warp tile m64 x n32,
// double-buffered ldmatrix fragment pipeline. 128 s-rows per CTA.
//   AS [0,      65536): A = bf16(mem+pos) 128x256, SWZB
//   WQ [65536, 131072): Wp half (128x256) / q tile (128x256), SWZB
//   KP [131072,196608): kp tile 128x256 bf16 (bias added, unnormalized), SWZB
#define OF_ROW  196608
#define OF_BSM  197120
#define OF_AMX  198144
#define OF_THR  198656
#define OF_WT   199168
#define OF_WO   199232
#define OF_BASE 199296
#define FU_SMEM 199424
__global__ __launch_bounds__(256, 1) void fused_kernel(
    const float* __restrict__ mem, const float* __restrict__ pos,
    const float* __restrict__ bp)
{
    extern __shared__ char sm[];
    const uint32_t smu = (uint32_t)__cvta_generic_to_shared(sm);
    char* AS = sm;
    char* WQ = sm + 65536;
    char* KP = sm + 131072;
    float*    rowss  = (float*)(sm + OF_ROW);      // [128] sumsq -> invnorm
    float*    bsm    = (float*)(sm + OF_BSM);      // [256]
    unsigned* amax_s = (unsigned*)(sm + OF_AMX);   // [128]
    float*    thr_s  = (float*)(sm + OF_THR);      // [128]
    unsigned* wtot   = (unsigned*)(sm + OF_WT);    // [8]
    unsigned* woff   = (unsigned*)(sm + OF_WO);    // [8]
    unsigned* base_s = (unsigned*)(sm + OF_BASE);

    const uint32_t AS_u = smu, WQ_u = smu + 65536, KP_u = smu + 131072;
    const int t = threadIdx.x, lane = t & 31, wid = t >> 5;
    const int g = lane >> 2, tid4 = lane & 3;
    const int wm = wid >> 2;          // 0..1  (m rows, 64 each)
    const int wn = wid & 3;           // 0..3  (j/l cols, 32 each)
    const int s0 = blockIdx.x * 128;
    const int n  = blockIdx.y;

    // ldmatrix per-lane address constants
    const int xL    = lane & 7;
    const int aLrow = (lane & 7) + ((lane >> 3) & 1) * 8;
    const int aDu   = lane >> 4;
    const int bLrow = (lane & 7) + (lane >> 4) * 8;
    const int bDu   = (lane >> 3) & 1;

    if (t < 128) rowss[t] = 0.f;
    bsm[t] = bp[t];

    // ---- stage Wp half 0 (async) ----
#pragma unroll
    for (int i = 0; i < 16; ++i) {
        const int id = t + i * 256, r = id >> 5, u = id & 31;
        cp16(WQ + SWZB(r, u), &g_wpb[(size_t)r * 256 + u * 8]);
    }
    cp_commit();

    // ---- stage A = bf16(mem+pos), SWZB (LDG overlaps cp.async) ----
#pragma unroll
    for (int i = 0; i < 16; ++i) {
        const int id = t + i * 256, r = id >> 5, u = id & 31;
        const size_t base = ((size_t)(s0 + r) * 8 + n) * 256 + u * 8;
        const float4 m0 = *(const float4*)&mem[base];
        const float4 m1 = *(const float4*)&mem[base + 4];
        const float4 p0 = *(const float4*)&pos[base];
        const float4 p1 = *(const float4*)&pos[base + 4];
        uint4 v;
        v.x = pkbf(m0.x + p0.x, m0.y + p0.y);
        v.y = pkbf(m0.z + p0.z, m0.w + p0.w);
        v.z = pkbf(m1.x + p1.x, m1.y + p1.y);
        v.w = pkbf(m1.z + p1.z, m1.w + p1.w);
        *(uint4*)(AS + SWZB(r, u)) = v;
    }

    // fragment smem base addresses
    uint32_t aBase[4], kpBase[4];
#pragma unroll
    for (int mf = 0; mf < 4; ++mf) {
        const int row = wm * 64 + mf * 16 + aLrow;
        aBase[mf]  = AS_u + (row << 9);
        kpBase[mf] = KP_u + (row << 9);
    }
    const uint32_t bBase0 = WQ_u + ((wn * 32 + bLrow) << 9);
    const uint32_t bBase1 = WQ_u + ((wn * 32 + 16 + bLrow) << 9);

    unsigned aF[2][4][4], bF[2][2][4];

#define LD_A(buf, kk, BASE)                                                       \
    {                                                                             \
        const uint32_t _o = (uint32_t)(((2 * (kk) + aDu) ^ xL) << 4);             \
        _Pragma("unroll")                                                         \
        for (int _mf = 0; _mf < 4; ++_mf) ldsm4(aF[buf][_mf], (BASE)[_mf] + _o);  \
    }
#define LD_B(buf, kk)                                                             \
    {                                                                             \
        const uint32_t _o = (uint32_t)(((2 * (kk) + bDu) ^ xL) << 4);             \
        ldsm4(bF[buf][0], bBase0 + _o);                                           \
        ldsm4(bF[buf][1], bBase1 + _o);                                           \
    }
#define MMA_STEP(buf, accv)                                                       \
    _Pragma("unroll")                                                             \
    for (int _mf = 0; _mf < 4; ++_mf)                                             \
        _Pragma("unroll")                                                         \
        for (int _nf = 0; _nf < 4; ++_nf)                                         \
            mma_bf16(accv[_mf][_nf], aF[buf][_mf],                                \
                     bF[buf][_nf >> 1][(_nf & 1) * 2],                            \
                     bF[buf][_nf >> 1][(_nf & 1) * 2 + 1]);

    // ================= Phase 1: kp = A @ Wp^T (+bias), two 128-col halves ========
#pragma unroll 1
    for (int h = 0; h < 2; ++h) {
        cp_wait0();
        __syncthreads();
        float acc[4][4][4];
#pragma unroll
        for (int mf = 0; mf < 4; ++mf)
#pragma unroll
            for (int nf = 0; nf < 4; ++nf)
#pragma unroll
                for (int c = 0; c < 4; ++c) acc[mf][nf][c] = 0.f;

        LD_B(0, 0);
        LD_A(0, 0, aBase);
#pragma unroll
        for (int kk = 0; kk < 16; ++kk) {
            const int cur = kk & 1;
            if (kk < 15) { LD_B(cur ^ 1, kk + 1); LD_A(cur ^ 1, kk + 1, aBase); }
            MMA_STEP(cur, acc);
        }
        __syncthreads();   // all warps done reading WQ

        // restage WQ: Wp half 1 (h==0) or q tile (h==1) — overlaps epilogue
        if (h == 0) {
#pragma unroll
            for (int i = 0; i < 16; ++i) {
                const int id = t + i * 256, r = id >> 5, u = id & 31;
                cp16(WQ + SWZB(r, u), &g_wpb[(size_t)(128 + r) * 256 + u * 8]);
            }
        } else {
#pragma unroll
            for (int i = 0; i < 16; ++i) {
                const int id = t + i * 256, r = id >> 5, u = id & 31;
                cp16(WQ + SWZB(r, u), &g_qb[((size_t)n * L_Q + r) * 256 + u * 8]);
            }
        }
        cp_commit();

        // epilogue: +bias, sum-sq, store bf16 kp tile
#pragma unroll
        for (int mf = 0; mf < 4; ++mf) {
            const int m0 = wm * 64 + mf * 16 + g, m1 = m0 + 8;
            float ss0 = 0.f, ss1 = 0.f;
#pragma unroll
            for (int nf = 0; nf < 4; ++nf) {
                const int jc = h * 128 + wn * 32 + nf * 8 + 2 * tid4;
                const float b0v = bsm[jc], b1v = bsm[jc + 1];
                const float v00 = acc[mf][nf][0] + b0v, v01 = acc[mf][nf][1] + b1v;
                const float v10 = acc[mf][nf][2] + b0v, v11 = acc[mf][nf][3] + b1v;
                ss0 += v00 * v00 + v01 * v01;
                ss1 += v10 * v10 + v11 * v11;
                *(unsigned*)(KP + KPB(m0, jc)) = pkbf(v00, v01);
                *(unsigned*)(KP + KPB(m1, jc)) = pkbf(v10, v11);
            }
            ss0 += __shfl_xor_sync(0xffffffffu, ss0, 1);
            ss0 += __shfl_xor_sync(0xffffffffu, ss0, 2);
            ss1 += __shfl_xor_sync(0xffffffffu, ss1, 1);
            ss1 += __shfl_xor_sync(0xffffffffu, ss1, 2);
            if (tid4 == 0) {
                atomicAdd(&rowss[m0], ss0);
                atomicAdd(&rowss[m1], ss1);
            }
        }
    }
    __syncthreads();
    if (t < 128) { rowss[t] = 1.0f / fmaxf(sqrtf(rowss[t]), 1e-12f); amax_s[t] = 0u; }
    cp_wait0();        // q tile staged
    __syncthreads();

    // ================= Phase 2: logits[s][l] = (KP . q) * invnorm[s] ============
    float acc[4][4][4];
#pragma unroll
    for (int mf = 0; mf < 4; ++mf)
#pragma unroll
        for (int nf = 0; nf < 4; ++nf)
#pragma unroll
            for (int c = 0; c < 4; ++c) acc[mf][nf][c] = 0.f;

    LD_B(0, 0);
    LD_A(0, 0, kpBase);
#pragma unroll
    for (int kk = 0; kk < 16; ++kk) {
        const int cur = kk & 1;
        if (kk < 15) { LD_B(cur ^ 1, kk + 1); LD_A(cur ^ 1, kk + 1, kpBase); }
        MMA_STEP(cur, acc);
    }

    // scale by 1/norm (rows = s)
#pragma unroll
    for (int mf = 0; mf < 4; ++mf) {
        const int r0 = wm * 64 + mf * 16 + g;
        const float inv0 = rowss[r0], inv1 = rowss[r0 + 8];
#pragma unroll
        for (int nf = 0; nf < 4; ++nf) {
            acc[mf][nf][0] *= inv0; acc[mf][nf][1] *= inv0;
            acc[mf][nf][2] *= inv1; acc[mf][nf][3] *= inv1;
        }
    }

    // CTA-local per-l max
#pragma unroll
    for (int nf = 0; nf < 4; ++nf) {
        float me = acc[0][nf][0], mo = acc[0][nf][1];
#pragma unroll
        for (int mf = 0; mf < 4; ++mf) {
            me = fmaxf(me, fmaxf(acc[mf][nf][0], acc[mf][nf][2]));
            mo = fmaxf(mo, fmaxf(acc[mf][nf][1], acc[mf][nf][3]));
        }
#pragma unroll
        for (int off = 4; off < 32; off <<= 1) {
            me = fmaxf(me, __shfl_xor_sync(0xffffffffu, me, off));
            mo = fmaxf(mo, __shfl_xor_sync(0xffffffffu, mo, off));
        }
        if (lane < 4) {
            const int lc = wn * 32 + nf * 8 + 2 * lane;
            atomicMax(&amax_s[lc],     fmap(me));
            atomicMax(&amax_s[lc + 1], fmap(mo));
        }
    }
    __syncthreads();
    if (t < 128) {
        atomicMax(&g_amax[t * 8 + n], amax_s[t]);
        thr_s[t] = funmap(amax_s[t]) - MARGIN;
    }
    __syncthreads();

    // candidate count + scan + pool write
    int cnt = 0;
#pragma unroll
    for (int mf = 0; mf < 4; ++mf)
#pragma unroll
        for (int nf = 0; nf < 4; ++nf)
#pragma unroll
            for (int c = 0; c < 4; ++c) {
                const int lc = wn * 32 + nf * 8 + 2 * tid4 + (c & 1);
                if (acc[mf][nf][c] >= thr_s[lc]) ++cnt;
            }
    int incl = cnt;
#pragma unroll
    for (int off = 1; off < 32; off <<= 1) {
        const int x = __shfl_up_sync(0xffffffffu, incl, off);
        if (lane >= off) incl += x;
    }
    if (lane == 31) wtot[wid] = (unsigned)incl;
    __syncthreads();
    if (t == 0) {
        unsigned tot = 0;
#pragma unroll
        for (int w = 0; w < 8; ++w) { woff[w] = tot; tot += wtot[w]; }
        *base_s = atomicAdd(&g_npool, tot);
    }
    __syncthreads();
    unsigned p = *base_s + woff[wid] + (unsigned)(incl - cnt);
#pragma unroll
    for (int mf = 0; mf < 4; ++mf)
#pragma unroll
        for (int nf = 0; nf < 4; ++nf)
#pragma unroll
            for (int c = 0; c < 4; ++c) {
                const int lc = wn * 32 + nf * 8 + 2 * tid4 + (c & 1);
                const float v = acc[mf][nf][c];
                if (v >= thr_s[lc]) {
                    const int sr = s0 + wm * 64 + mf * 16 + g + ((c >= 2) ? 8 : 0);
                    if (p < POOL_CAP)
                        g_pool[p] = make_uint2(((unsigned)sr << 10) |
                                               ((unsigned)lc << 3) | (unsigned)n,
                                               __float_as_uint(v));
                    ++p;
                }
            }
}

// ---------------- K4: filter pool against global approx max ----------------
__global__ __launch_bounds__(256) void filter_kernel()
{
    __shared__ float thr_s[LN_ROWS];
    const int t = threadIdx.x;
    for (int i = t; i < LN_ROWS; i += 256) thr_s[i] = funmap(g_amax[i]) - MARGIN;
    __syncthreads();
    const unsigned np = min(g_npool, (unsigned)POOL_CAP);
    for (unsigned idx = blockIdx.x * 256 + t; idx < np; idx += gridDim.x * 256) {
        const uint2 e = g_pool[idx];
        const unsigned l = (e.x >> 3) & 127u, n = e.x & 7u;
        if (__uint_as_float(e.y) >= thr_s[l * 8 + n]) {
            const unsigned pp = atomicAdd(&g_ncand, 1u);
            if (pp < CAND_CAP) g_cand[pp] = e.x;
        }
    }
}

// ---------------- K5: exact fp32 rescore, batched 32 candidates/CTA ----------------
#define RS_SMEM (32768 + 32896 + 32896)
__global__ __launch_bounds__(256, 1) void rescore_kernel(
    const float* __restrict__ mem, const float* __restrict__ pos,
    const float* __restrict__ Wp,  const float* __restrict__ bp)
{
    extern __shared__ char rsm[];
    float* A   = (float*)rsm;                    // [32][256]
    float* WT  = (float*)(rsm + 32768);          // [kk][o], stride 257
    float* KPS = (float*)(rsm + 65664);          // [ci][t], stride 257
    __shared__ unsigned meta[32];
    __shared__ unsigned count_s;

    const int t = threadIdx.x, lane = t & 31, wid = t >> 5;
    if (t == 0) count_s = min(g_ncand, (unsigned)CAND_CAP);
    __syncthreads();
    const unsigned count = count_s;
    const unsigned nchunks = (count + 31u) >> 5;

    for (unsigned chunk = blockIdx.x; chunk < nchunks; chunk += gridDim.x) {
        __syncthreads();
        if (t < 32)
            meta[t] = (chunk * 32u + t < count) ? g_cand[chunk * 32u + t] : 0xFFFFFFFFu;
        __syncthreads();
#pragma unroll 4
        for (int ci = 0; ci < 32; ++ci) {
            const unsigned pk = meta[ci];
            if (pk != 0xFFFFFFFFu) {
                const size_t rowk = ((size_t)(pk >> 10) * 8 + (pk & 7u)) * 256;
                A[ci * 256 + t] = mem[rowk + t] + pos[rowk + t];
            }
        }
        float acc[32];
        const float bias = bp[t];
#pragma unroll
        for (int ci = 0; ci < 32; ++ci) acc[ci] = bias;

        for (int kt = 0; kt < 8; ++kt) {
            __syncthreads();
#pragma unroll
            for (int i = 0; i < 8; ++i) {
                const int id = t + i * 256, o = id >> 3, k4 = id & 7;
                const float4 w = *(const float4*)&Wp[(size_t)o * 256 + kt * 32 + k4 * 4];
                WT[(k4 * 4 + 0) * 257 + o] = w.x;
                WT[(k4 * 4 + 1) * 257 + o] = w.y;
                WT[(k4 * 4 + 2) * 257 + o] = w.z;
                WT[(k4 * 4 + 3) * 257 + o] = w.w;
            }
            __syncthreads();
            float wt[32];
#pragma unroll
            for (int kk = 0; kk < 32; ++kk) wt[kk] = WT[kk * 257 + t];
#pragma unroll 4
            for (int ci = 0; ci < 32; ++ci) {
                const float4* a4 = (const float4*)&A[ci * 256 + kt * 32];
#pragma unroll
                for (int q = 0; q < 8; ++q) {
                    const float4 av = a4[q];
                    acc[ci] += av.x * wt[q * 4 + 0] + av.y * wt[q * 4 + 1]
                             + av.z * wt[q * 4 + 2] + av.w * wt[q * 4 + 3];
                }
            }
        }
        __syncthreads();
#pragma unroll
        for (int ci = 0; ci < 32; ++ci) KPS[ci * 257 + t] = acc[ci];
        __syncthreads();
#pragma unroll
        for (int cc = 0; cc < 4; ++cc) {
            const int ci = wid * 4 + cc;
            const unsigned pk = meta[ci];
            if (pk == 0xFFFFFFFFu) continue;
            const unsigned s = pk >> 10, l = (pk >> 3) & 127u, n = pk & 7u;
            const float* qrow = &g_qproj[((size_t)l * 8 + n) * 256];
            float ss = 0.f, qd = 0.f;
#pragma unroll
            for (int j = 0; j < 8; ++j) {
                const float kv = KPS[ci * 257 + lane + 32 * j];
                ss += kv * kv;
                qd += qrow[lane + 32 * j] * kv;
            }
#pragma unroll
            for (int off = 16; off > 0; off >>= 1) {
                ss += __shfl_xor_sync(0xffffffffu, ss, off);
                qd += __shfl_xor_sync(0xffffffffu, qd, off);
            }
            if (lane == 0) {
                const float logit = qd / fmaxf(sqrtf(ss), 1e-12f);
                const unsigned long long key =
                    ((unsigned long long)fmap(logit) << 32) |
                    (unsigned long long)(0xFFFFFFFFu - s);
                atomicMax(&g_argmax[l * 8 + n], key);
            }
        }
    }
}

// ---------------- K6: batched finalize — 64 CTAs x 16 rows ----------------
#define FIN_SMEM (16384 + 16384 + 32896)
__global__ __launch_bounds__(256, 1) void finalize_kernel(
    const float* __restrict__ tgt,   const float* __restrict__ memory,
    const float* __restrict__ pos,
    const float* __restrict__ Wp,    const float* __restrict__ bp,
    const float* __restrict__ Wv,    const float* __restrict__ bv,
    const float* __restrict__ Wo,    const float* __restrict__ bo,
    const float* __restrict__ gamma, const float* __restrict__ beta,
    float* __restrict__ out)
{
    extern __shared__ char fsm[];
    float* BUF0 = (float*)fsm;                    // [16][256]
    float* BUF1 = (float*)(fsm + 16384);          // [16][256]
    float* WT   = (float*)(fsm + 32768);          // [32][257]
    __shared__ int sel_s[16];

    const int t = threadIdx.x, lane = t & 31, wid = t >> 5;
    const int base = blockIdx.x * 16;

    if (t < 16) {
        const unsigned long long key = g_argmax[base + t];
        sel_s[t] = (int)(0xFFFFFFFFu - (unsigned)(key & 0xFFFFFFFFull));
    }
    __syncthreads();
#pragma unroll
    for (int r = 0; r < 16; ++r) {
        const size_t rowk = ((size_t)sel_s[r] * 8 + ((base + r) & 7)) * 256;
        BUF0[r * 256 + t] = memory[rowk + t] + pos[rowk + t];
    }
    const float* Ws[3] = {Wp, Wv, Wo};
    const float* bs[3] = {bp, bv, bo};
#pragma unroll
    for (int layer = 0; layer < 3; ++layer) {
        const float* W   = Ws[layer];
        float* INB  = (layer & 1) ? BUF1 : BUF0;
        float* OUTB = (layer & 1) ? BUF0 : BUF1;
        float acc[16];
#pragma unroll
        for (int r = 0; r < 16; ++r) acc[r] = 0.f;
        for (int kt = 0; kt < 8; ++kt) {
            __syncthreads();
#pragma unroll
            for (int i = 0; i < 8; ++i) {
                const int id = t + i * 256, o = id >> 3, k4 = id & 7;
                const float4 w = *(const float4*)&W[(size_t)o * 256 + kt * 32 + k4 * 4];
                WT[(k4 * 4 + 0) * 257 + o] = w.x;
                WT[(k4 * 4 + 1) * 257 + o] = w.y;
                WT[(k4 * 4 + 2) * 257 + o] = w.z;
                WT[(k4 * 4 + 3) * 257 + o] = w.w;
            }
            __syncthreads();
            float wt[32];
#pragma unroll
            for (int kk = 0; kk < 32; ++kk) wt[kk] = WT[kk * 257 + t];
#pragma unroll
            for (int r = 0; r < 16; ++r) {
                const float4* a4 = (const float4*)&INB[r * 256 + kt * 32];
#pragma unroll
                for (int q = 0; q < 8; ++q) {
                    const float4 av = a4[q];
                    acc[r] += av.x * wt[q * 4 + 0] + av.y * wt[q * 4 + 1]
                            + av.z * wt[q * 4 + 2] + av.w * wt[q * 4 + 3];
                }
            }
        }
        __syncthreads();
        const float bias = bs[layer][t];
#pragma unroll
        for (int r = 0; r < 16; ++r)
            OUTB[r * 256 + t] = acc[r] + bias;
    }
    __syncthreads();
#pragma unroll
    for (int rr = 0; rr < 2; ++rr) {
        const int r = wid * 2 + rr;
        const int pair = base + r;
        float xv[8];
        float s = 0.f, s2 = 0.f;
#pragma unroll
        for (int j = 0; j < 8; ++j) {
            const int c = lane + 32 * j;
            xv[j] = tgt[(size_t)pair * 256 + c] + BUF1[r * 256 + c];
            s  += xv[j];
            s2 += xv[j] * xv[j];
        }
#pragma unroll
        for (int off = 16; off > 0; off >>= 1) {
            s  += __shfl_xor_sync(0xffffffffu, s,  off);
            s2 += __shfl_xor_sync(0xffffffffu, s2, off);
        }
        const float mu   = s * (1.0f / 256.0f);
        const float var  = s2 * (1.0f / 256.0f) - mu * mu;
        const float rstd = rsqrtf(var + 1e-5f);
#pragma unroll
        for (int j = 0; j < 8; ++j) {
            const int c = lane + 32 * j;
            out[(size_t)pair * 256 + c] = (xv[j] - mu) * rstd * gamma[c] + beta[c];
        }
    }
}

// ---------------- launch ----------------
extern "C" void kernel_launch(void* const* d_in, const int* in_sizes, int n_in,
                              void* d_out, int out_size)
{
    const float* tgt       = (const float*)d_in[0];
    const float* memory    = (const float*)d_in[1];
    const float* pos       = (const float*)d_in[2];
    const float* query_pos = (const float*)d_in[3];
    const float* Wq        = (const float*)d_in[4];
    const float* bq        = (const float*)d_in[5];
    const float* Wp        = (const float*)d_in[6];
    const float* bp        = (const float*)d_in[7];
    const float* Wv        = (const float*)d_in[8];
    const float* bv        = (const float*)d_in[9];
    const float* Wo        = (const float*)d_in[10];
    const float* bo        = (const float*)d_in[11];
    const float* gamma     = (const float*)d_in[12];
    const float* beta      = (const float*)d_in[13];
    float* out             = (float*)d_out;

    cudaFuncSetAttribute(fused_kernel,
                         cudaFuncAttributeMaxDynamicSharedMemorySize, FU_SMEM);
    cudaFuncSetAttribute(rescore_kernel,
                         cudaFuncAttributeMaxDynamicSharedMemorySize, RS_SMEM);
    cudaFuncSetAttribute(finalize_kernel,
                         cudaFuncAttributeMaxDynamicSharedMemorySize, FIN_SMEM);

    init_kernel<<<256, 256>>>(Wp);
    qproj_kernel<<<LN_ROWS / 8, 256>>>(tgt, query_pos, Wq, bq);
    fused_kernel<<<dim3(S_P / 128, N_B), 256, FU_SMEM>>>(memory, pos, bp);
    filter_kernel<<<512, 256>>>();
    rescore_kernel<<<148, 256, RS_SMEM>>>(memory, pos, Wp, bp);
    finalize_kernel<<<LN_ROWS / 16, 256, FIN_SMEM>>>(tgt, memory, pos, Wp, bp,
                                                     Wv, bv, Wo, bo,
                                                     gamma, beta, out);
}